// round 14
// baseline (speedup 1.0000x reference)
#include <cuda_runtime.h>
#include <cuda_bf16.h>

// SmallVDSR: 20-layer 3x3 conv stack on [8,1,512,512] fp32.
//   conv1: 1->8 + relu        (vectorized, IC=1)
//   conv2..19: 18x (8->8+relu) (hot kernel)
//   conv20: 8->1, no relu     (vectorized, OC=1)
//
// R13 hot kernel: R12 minus the constant port.
//   ALL weight oc-pairs staged to smem (u64 [ic][tap][pair]); inner loop is
//   pure LDS (broadcast) + FFMA2. ic loop unrolled x4. 5 CTAs/SM pinned.

#define H 512
#define W 512
#define NB 8
#define PLANE (H * W)

typedef unsigned long long u64;

__device__ float g_bufA[NB * 8 * PLANE];
__device__ float g_bufB[NB * 8 * PLANE];

// Packed weights, layout [l][ic][tap][oc] (oc contiguous):
//   [0 .. 10368)        mid layers
//   [10368 .. 10440)    w1  [tap][oc]
//   [10440 .. 10512)    w20 [ic][tap]
#define CW_MID  0
#define CW_W1   (18 * 8 * 9 * 8)
#define CW_W20  (CW_W1 + 72)
__constant__ __align__(16) float c_w[CW_W20 + 72];
__device__   __align__(16) float g_wpack[CW_W20 + 72];

__device__ __forceinline__ u64 pack_dup(float v) {
    u64 r;
    asm("mov.b64 %0, {%1, %1};" : "=l"(r) : "f"(v));
    return r;
}
__device__ __forceinline__ void fma2(u64& acc, u64 a, u64 b) {
    asm("fma.rn.f32x2 %0, %1, %2, %0;" : "+l"(acc) : "l"(a), "l"(b));
}
__device__ __forceinline__ void unpack2(float& lo, float& hi, u64 v) {
    asm("mov.b64 {%0, %1}, %2;" : "=f"(lo), "=f"(hi) : "l"(v));
}

__global__ void repack_weights_kernel(const float* __restrict__ wmid,
                                      const float* __restrict__ w1,
                                      const float* __restrict__ w20)
{
    int idx = blockIdx.x * blockDim.x + threadIdx.x;
    if (idx < 18 * 8 * 9 * 8) {
        int oc = idx & 7;
        int t  = (idx >> 3) % 9;
        int ic = ((idx >> 3) / 9) & 7;
        int l  = idx / 576;
        g_wpack[idx] = wmid[l * 576 + (oc * 8 + ic) * 9 + t];   // [l][oc][ic][k]
    } else if (idx < CW_W20) {
        int j = idx - CW_W1;               // [tap][oc]
        int oc = j & 7;
        int t  = j >> 3;
        g_wpack[idx] = w1[oc * 9 + t];                           // [oc][0][k]
    } else if (idx < CW_W20 + 72) {
        int j = idx - CW_W20;              // [ic][tap]
        int t  = j % 9;
        int ic = j / 9;
        g_wpack[idx] = w20[ic * 9 + t];                          // [0][ic][k]
    }
}

// ---------------------------------------------------------------------------
// Shared staging: 130x10 halo tile per ic into smem (pitch 132).
// ---------------------------------------------------------------------------
template <int IC>
__device__ __forceinline__ void stage_tile(const float* __restrict__ inb,
                                           float* __restrict__ s_in,
                                           int gx0, int gy0, int tid)
{
    constexpr int PITCH = 132;
    constexpr int STILE = PITCH * 10;
    const int wid  = tid >> 5;
    const int lane = tid & 31;
    #pragma unroll 1
    for (int ic = 0; ic < IC; ++ic) {
        const float* src = inb + ic * PLANE;
        float* dst = s_in + ic * STILE;
        #pragma unroll
        for (int rr0 = 0; rr0 < 2; ++rr0) {
            int rr = wid + rr0 * 8;
            if (rr0 == 1 && wid >= 2) continue;    // rows 8,9 by warps 0,1
            int gy = gy0 + rr - 1;
            bool yok = (gy >= 0) && (gy < H);
            int rb = gy << 9;
            #pragma unroll
            for (int cc = 0; cc < 5; ++cc) {
                int c = lane + cc * 32;
                if (cc == 4 && lane >= 2) break;   // cols 0..129
                int gx = gx0 + c - 1;
                bool ok = yok && (gx >= 0) && (gx < W);
                dst[rr * PITCH + c] = ok ? src[rb + gx] : 0.0f;
            }
        }
    }
}

// ---------------------------------------------------------------------------
// Vectorized conv, OC=8 (f32x2 oc-pairs). IC = 8 (mid) or 1 (conv1).
// Block 256. Tile 128x8. Thread: 4 px x 8 oc.
// All weights from smem as u64 oc-pairs (LDS.128 broadcast only).
// ---------------------------------------------------------------------------
template <int IC, int UNROLL, int MINB>
__global__ void __launch_bounds__(256, MINB)
convv8_kernel(const float* __restrict__ in,
              float* __restrict__ out,
              int wofs)
{
    constexpr int PITCH = 132;
    constexpr int STILE = PITCH * 10;

    __shared__ __align__(16) float s_in[IC * STILE];
    __shared__ __align__(16) u64   s_w[IC * 36];   // [ic][tap][pair0..3]

    const int tid  = threadIdx.x;
    const int tx   = tid & 31;
    const int ty   = tid >> 5;
    const int n    = blockIdx.z;
    const int gx0  = blockIdx.x * 128;
    const int gy0  = blockIdx.y * 8;

    // stage ALL weight pairs into smem (u64 view of [ic][tap][oc] packing)
    {
        const u64* wsrc = (const u64*)(g_wpack + wofs);
        #pragma unroll
        for (int i = tid; i < IC * 36; i += 256)
            s_w[i] = wsrc[i];
    }

    stage_tile<IC>(in + (size_t)n * IC * PLANE, s_in, gx0, gy0, tid);
    __syncthreads();

    u64 acc2[4][4];   // [oc-pair][px]
    #pragma unroll
    for (int p = 0; p < 4; ++p)
        #pragma unroll
        for (int j = 0; j < 4; ++j)
            acc2[p][j] = 0ull;

    const float* si0 = &s_in[ty * PITCH + 4 * tx];

    #pragma unroll UNROLL
    for (int ic = 0; ic < IC; ++ic) {
        const float* si  = si0 + ic * STILE;
        const u64*   swp = &s_w[ic * 36];

        #pragma unroll
        for (int r = 0; r < 3; ++r) {
            float4 v03 = *(const float4*)(si + r * PITCH);
            float2 v45 = *(const float2*)(si + r * PITCH + 4);
            u64 dd[6];
            dd[0] = pack_dup(v03.x);
            dd[1] = pack_dup(v03.y);
            dd[2] = pack_dup(v03.z);
            dd[3] = pack_dup(v03.w);
            dd[4] = pack_dup(v45.x);
            dd[5] = pack_dup(v45.y);

            #pragma unroll
            for (int kx = 0; kx < 3; ++kx) {
                const int t = r * 3 + kx;
                ulonglong2 wpA = *(const ulonglong2*)&swp[t * 4];      // oc01, oc23
                ulonglong2 wpB = *(const ulonglong2*)&swp[t * 4 + 2];  // oc45, oc67
                #pragma unroll
                for (int j = 0; j < 4; ++j) {
                    u64 u = dd[j + kx];
                    fma2(acc2[0][j], u, wpA.x);
                    fma2(acc2[1][j], u, wpA.y);
                    fma2(acc2[2][j], u, wpB.x);
                    fma2(acc2[3][j], u, wpB.y);
                }
            }
        }
    }

    float* outb = out + (size_t)n * 8 * PLANE + ((gy0 + ty) << 9) + gx0 + 4 * tx;
    #pragma unroll
    for (int p = 0; p < 4; ++p) {
        float l0, h0, l1, h1, l2, h2, l3, h3;
        unpack2(l0, h0, acc2[p][0]);
        unpack2(l1, h1, acc2[p][1]);
        unpack2(l2, h2, acc2[p][2]);
        unpack2(l3, h3, acc2[p][3]);
        float4 oL, oH;
        oL.x = fmaxf(l0, 0.0f); oL.y = fmaxf(l1, 0.0f);
        oL.z = fmaxf(l2, 0.0f); oL.w = fmaxf(l3, 0.0f);
        oH.x = fmaxf(h0, 0.0f); oH.y = fmaxf(h1, 0.0f);
        oH.z = fmaxf(h2, 0.0f); oH.w = fmaxf(h3, 0.0f);
        *(float4*)(outb + (2 * p + 0) * PLANE) = oL;
        *(float4*)(outb + (2 * p + 1) * PLANE) = oH;
    }
}

// ---------------------------------------------------------------------------
// Vectorized conv20: IC=8 -> OC=1, no relu. Scalar accs (4 px).
// ---------------------------------------------------------------------------
__global__ void __launch_bounds__(256, 4)
convv20_kernel(const float* __restrict__ in,
               float* __restrict__ out)
{
    constexpr int PITCH = 132;
    constexpr int STILE = PITCH * 10;

    __shared__ __align__(16) float s_in[8 * STILE];

    const int tid  = threadIdx.x;
    const int tx   = tid & 31;
    const int ty   = tid >> 5;
    const int n    = blockIdx.z;
    const int gx0  = blockIdx.x * 128;
    const int gy0  = blockIdx.y * 8;

    stage_tile<8>(in + (size_t)n * 8 * PLANE, s_in, gx0, gy0, tid);
    __syncthreads();

    float acc[4] = {0.0f, 0.0f, 0.0f, 0.0f};
    const float* si0 = &s_in[ty * PITCH + 4 * tx];

    #pragma unroll 2
    for (int ic = 0; ic < 8; ++ic) {
        const float* si = si0 + ic * STILE;
        const int wb_ic = CW_W20 + ic * 9;

        #pragma unroll
        for (int r = 0; r < 3; ++r) {
            float4 v03 = *(const float4*)(si + r * PITCH);
            float2 v45 = *(const float2*)(si + r * PITCH + 4);
            float v[6] = {v03.x, v03.y, v03.z, v03.w, v45.x, v45.y};
            #pragma unroll
            for (int kx = 0; kx < 3; ++kx) {
                float w = c_w[wb_ic + r * 3 + kx];
                #pragma unroll
                for (int j = 0; j < 4; ++j)
                    acc[j] = fmaf(v[j + kx], w, acc[j]);
            }
        }
    }

    float* outb = out + (size_t)n * PLANE + ((gy0 + ty) << 9) + gx0 + 4 * tx;
    float4 o;
    o.x = acc[0]; o.y = acc[1]; o.z = acc[2]; o.w = acc[3];
    *(float4*)outb = o;
}

extern "C" void kernel_launch(void* const* d_in, const int* in_sizes, int n_in,
                              void* d_out, int out_size)
{
    const float* x    = (const float*)d_in[0];  // [8,1,512,512]
    const float* w1   = (const float*)d_in[1];  // [8,1,3,3]
    const float* wmid = (const float*)d_in[2];  // [18,8,8,3,3]
    const float* w20  = (const float*)d_in[3];  // [1,8,3,3]
    float* out = (float*)d_out;                 // [8,1,512,512]

    float* bufA = nullptr;
    float* bufB = nullptr;
    float* wpack = nullptr;
    cudaGetSymbolAddress((void**)&bufA, g_bufA);
    cudaGetSymbolAddress((void**)&bufB, g_bufB);
    cudaGetSymbolAddress((void**)&wpack, g_wpack);

    // repack all weights -> g_wpack; conv20 still reads the constant bank
    const int nW = CW_W20 + 72;
    repack_weights_kernel<<<(nW + 255) / 256, 256>>>(wmid, w1, w20);
    cudaMemcpyToSymbolAsync(c_w, wpack, nW * sizeof(float), 0,
                            cudaMemcpyDeviceToDevice, 0);

    dim3 grid(W / 128, H / 8, NB);

    // conv1: 1 -> 8, relu
    convv8_kernel<1, 1, 4><<<grid, 256>>>(x, bufA, CW_W1);

    // conv2..19: 18x 8 -> 8, relu (all-smem weights, ic-unroll-4, occ-5)
    float* src = bufA;
    float* dst = bufB;
    for (int l = 0; l < 18; ++l) {
        convv8_kernel<8, 4, 5><<<grid, 256>>>(src, dst, l * 576);
        float* t = src; src = dst; dst = t;
    }

    // conv20: 8 -> 1, no relu
    convv20_kernel<<<grid, 256>>>(src, out);
}

// round 15
// speedup vs baseline: 1.0011x; 1.0011x over previous
#include <cuda_runtime.h>
#include <cuda_bf16.h>

// SmallVDSR: 20-layer 3x3 conv stack on [8,1,512,512] fp32.
//   conv1: 1->8 + relu        (vectorized, IC=1)
//   conv2..19: 18x (8->8+relu) (hot kernel)
//   conv20: 8->1, no relu     (vectorized, OC=1)
//
// R13 hot kernel: R12 minus the constant port.
//   ALL weight oc-pairs staged to smem (u64 [ic][tap][pair]); inner loop is
//   pure LDS (broadcast) + FFMA2. ic loop unrolled x4. 5 CTAs/SM pinned.

#define H 512
#define W 512
#define NB 8
#define PLANE (H * W)

typedef unsigned long long u64;

__device__ float g_bufA[NB * 8 * PLANE];
__device__ float g_bufB[NB * 8 * PLANE];

// Packed weights, layout [l][ic][tap][oc] (oc contiguous):
//   [0 .. 10368)        mid layers
//   [10368 .. 10440)    w1  [tap][oc]
//   [10440 .. 10512)    w20 [ic][tap]
#define CW_MID  0
#define CW_W1   (18 * 8 * 9 * 8)
#define CW_W20  (CW_W1 + 72)
__constant__ __align__(16) float c_w[CW_W20 + 72];
__device__   __align__(16) float g_wpack[CW_W20 + 72];

__device__ __forceinline__ u64 pack_dup(float v) {
    u64 r;
    asm("mov.b64 %0, {%1, %1};" : "=l"(r) : "f"(v));
    return r;
}
__device__ __forceinline__ void fma2(u64& acc, u64 a, u64 b) {
    asm("fma.rn.f32x2 %0, %1, %2, %0;" : "+l"(acc) : "l"(a), "l"(b));
}
__device__ __forceinline__ void unpack2(float& lo, float& hi, u64 v) {
    asm("mov.b64 {%0, %1}, %2;" : "=f"(lo), "=f"(hi) : "l"(v));
}

__global__ void repack_weights_kernel(const float* __restrict__ wmid,
                                      const float* __restrict__ w1,
                                      const float* __restrict__ w20)
{
    int idx = blockIdx.x * blockDim.x + threadIdx.x;
    if (idx < 18 * 8 * 9 * 8) {
        int oc = idx & 7;
        int t  = (idx >> 3) % 9;
        int ic = ((idx >> 3) / 9) & 7;
        int l  = idx / 576;
        g_wpack[idx] = wmid[l * 576 + (oc * 8 + ic) * 9 + t];   // [l][oc][ic][k]
    } else if (idx < CW_W20) {
        int j = idx - CW_W1;               // [tap][oc]
        int oc = j & 7;
        int t  = j >> 3;
        g_wpack[idx] = w1[oc * 9 + t];                           // [oc][0][k]
    } else if (idx < CW_W20 + 72) {
        int j = idx - CW_W20;              // [ic][tap]
        int t  = j % 9;
        int ic = j / 9;
        g_wpack[idx] = w20[ic * 9 + t];                          // [0][ic][k]
    }
}

// ---------------------------------------------------------------------------
// Shared staging: 130x10 halo tile per ic into smem (pitch 132).
// ---------------------------------------------------------------------------
template <int IC>
__device__ __forceinline__ void stage_tile(const float* __restrict__ inb,
                                           float* __restrict__ s_in,
                                           int gx0, int gy0, int tid)
{
    constexpr int PITCH = 132;
    constexpr int STILE = PITCH * 10;
    const int wid  = tid >> 5;
    const int lane = tid & 31;
    #pragma unroll 1
    for (int ic = 0; ic < IC; ++ic) {
        const float* src = inb + ic * PLANE;
        float* dst = s_in + ic * STILE;
        #pragma unroll
        for (int rr0 = 0; rr0 < 2; ++rr0) {
            int rr = wid + rr0 * 8;
            if (rr0 == 1 && wid >= 2) continue;    // rows 8,9 by warps 0,1
            int gy = gy0 + rr - 1;
            bool yok = (gy >= 0) && (gy < H);
            int rb = gy << 9;
            #pragma unroll
            for (int cc = 0; cc < 5; ++cc) {
                int c = lane + cc * 32;
                if (cc == 4 && lane >= 2) break;   // cols 0..129
                int gx = gx0 + c - 1;
                bool ok = yok && (gx >= 0) && (gx < W);
                dst[rr * PITCH + c] = ok ? src[rb + gx] : 0.0f;
            }
        }
    }
}

// ---------------------------------------------------------------------------
// Vectorized conv, OC=8 (f32x2 oc-pairs). IC = 8 (mid) or 1 (conv1).
// Block 256. Tile 128x8. Thread: 4 px x 8 oc.
// All weights from smem as u64 oc-pairs (LDS.128 broadcast only).
// ---------------------------------------------------------------------------
template <int IC, int UNROLL, int MINB>
__global__ void __launch_bounds__(256, MINB)
convv8_kernel(const float* __restrict__ in,
              float* __restrict__ out,
              int wofs)
{
    constexpr int PITCH = 132;
    constexpr int STILE = PITCH * 10;

    __shared__ __align__(16) float s_in[IC * STILE];
    __shared__ __align__(16) u64   s_w[IC * 36];   // [ic][tap][pair0..3]

    const int tid  = threadIdx.x;
    const int tx   = tid & 31;
    const int ty   = tid >> 5;
    const int n    = blockIdx.z;
    const int gx0  = blockIdx.x * 128;
    const int gy0  = blockIdx.y * 8;

    // stage ALL weight pairs into smem (u64 view of [ic][tap][oc] packing)
    {
        const u64* wsrc = (const u64*)(g_wpack + wofs);
        #pragma unroll
        for (int i = tid; i < IC * 36; i += 256)
            s_w[i] = wsrc[i];
    }

    stage_tile<IC>(in + (size_t)n * IC * PLANE, s_in, gx0, gy0, tid);
    __syncthreads();

    u64 acc2[4][4];   // [oc-pair][px]
    #pragma unroll
    for (int p = 0; p < 4; ++p)
        #pragma unroll
        for (int j = 0; j < 4; ++j)
            acc2[p][j] = 0ull;

    const float* si0 = &s_in[ty * PITCH + 4 * tx];

    #pragma unroll UNROLL
    for (int ic = 0; ic < IC; ++ic) {
        const float* si  = si0 + ic * STILE;
        const u64*   swp = &s_w[ic * 36];

        #pragma unroll
        for (int r = 0; r < 3; ++r) {
            float4 v03 = *(const float4*)(si + r * PITCH);
            float2 v45 = *(const float2*)(si + r * PITCH + 4);
            u64 dd[6];
            dd[0] = pack_dup(v03.x);
            dd[1] = pack_dup(v03.y);
            dd[2] = pack_dup(v03.z);
            dd[3] = pack_dup(v03.w);
            dd[4] = pack_dup(v45.x);
            dd[5] = pack_dup(v45.y);

            #pragma unroll
            for (int kx = 0; kx < 3; ++kx) {
                const int t = r * 3 + kx;
                ulonglong2 wpA = *(const ulonglong2*)&swp[t * 4];      // oc01, oc23
                ulonglong2 wpB = *(const ulonglong2*)&swp[t * 4 + 2];  // oc45, oc67
                #pragma unroll
                for (int j = 0; j < 4; ++j) {
                    u64 u = dd[j + kx];
                    fma2(acc2[0][j], u, wpA.x);
                    fma2(acc2[1][j], u, wpA.y);
                    fma2(acc2[2][j], u, wpB.x);
                    fma2(acc2[3][j], u, wpB.y);
                }
            }
        }
    }

    float* outb = out + (size_t)n * 8 * PLANE + ((gy0 + ty) << 9) + gx0 + 4 * tx;
    #pragma unroll
    for (int p = 0; p < 4; ++p) {
        float l0, h0, l1, h1, l2, h2, l3, h3;
        unpack2(l0, h0, acc2[p][0]);
        unpack2(l1, h1, acc2[p][1]);
        unpack2(l2, h2, acc2[p][2]);
        unpack2(l3, h3, acc2[p][3]);
        float4 oL, oH;
        oL.x = fmaxf(l0, 0.0f); oL.y = fmaxf(l1, 0.0f);
        oL.z = fmaxf(l2, 0.0f); oL.w = fmaxf(l3, 0.0f);
        oH.x = fmaxf(h0, 0.0f); oH.y = fmaxf(h1, 0.0f);
        oH.z = fmaxf(h2, 0.0f); oH.w = fmaxf(h3, 0.0f);
        *(float4*)(outb + (2 * p + 0) * PLANE) = oL;
        *(float4*)(outb + (2 * p + 1) * PLANE) = oH;
    }
}

// ---------------------------------------------------------------------------
// Vectorized conv20: IC=8 -> OC=1, no relu. Scalar accs (4 px).
// ---------------------------------------------------------------------------
__global__ void __launch_bounds__(256, 4)
convv20_kernel(const float* __restrict__ in,
               float* __restrict__ out)
{
    constexpr int PITCH = 132;
    constexpr int STILE = PITCH * 10;

    __shared__ __align__(16) float s_in[8 * STILE];

    const int tid  = threadIdx.x;
    const int tx   = tid & 31;
    const int ty   = tid >> 5;
    const int n    = blockIdx.z;
    const int gx0  = blockIdx.x * 128;
    const int gy0  = blockIdx.y * 8;

    stage_tile<8>(in + (size_t)n * 8 * PLANE, s_in, gx0, gy0, tid);
    __syncthreads();

    float acc[4] = {0.0f, 0.0f, 0.0f, 0.0f};
    const float* si0 = &s_in[ty * PITCH + 4 * tx];

    #pragma unroll 2
    for (int ic = 0; ic < 8; ++ic) {
        const float* si = si0 + ic * STILE;
        const int wb_ic = CW_W20 + ic * 9;

        #pragma unroll
        for (int r = 0; r < 3; ++r) {
            float4 v03 = *(const float4*)(si + r * PITCH);
            float2 v45 = *(const float2*)(si + r * PITCH + 4);
            float v[6] = {v03.x, v03.y, v03.z, v03.w, v45.x, v45.y};
            #pragma unroll
            for (int kx = 0; kx < 3; ++kx) {
                float w = c_w[wb_ic + r * 3 + kx];
                #pragma unroll
                for (int j = 0; j < 4; ++j)
                    acc[j] = fmaf(v[j + kx], w, acc[j]);
            }
        }
    }

    float* outb = out + (size_t)n * PLANE + ((gy0 + ty) << 9) + gx0 + 4 * tx;
    float4 o;
    o.x = acc[0]; o.y = acc[1]; o.z = acc[2]; o.w = acc[3];
    *(float4*)outb = o;
}

extern "C" void kernel_launch(void* const* d_in, const int* in_sizes, int n_in,
                              void* d_out, int out_size)
{
    const float* x    = (const float*)d_in[0];  // [8,1,512,512]
    const float* w1   = (const float*)d_in[1];  // [8,1,3,3]
    const float* wmid = (const float*)d_in[2];  // [18,8,8,3,3]
    const float* w20  = (const float*)d_in[3];  // [1,8,3,3]
    float* out = (float*)d_out;                 // [8,1,512,512]

    float* bufA = nullptr;
    float* bufB = nullptr;
    float* wpack = nullptr;
    cudaGetSymbolAddress((void**)&bufA, g_bufA);
    cudaGetSymbolAddress((void**)&bufB, g_bufB);
    cudaGetSymbolAddress((void**)&wpack, g_wpack);

    // repack all weights -> g_wpack; conv20 still reads the constant bank
    const int nW = CW_W20 + 72;
    repack_weights_kernel<<<(nW + 255) / 256, 256>>>(wmid, w1, w20);
    cudaMemcpyToSymbolAsync(c_w, wpack, nW * sizeof(float), 0,
                            cudaMemcpyDeviceToDevice, 0);

    dim3 grid(W / 128, H / 8, NB);

    // conv1: 1 -> 8, relu
    convv8_kernel<1, 1, 4><<<grid, 256>>>(x, bufA, CW_W1);

    // conv2..19: 18x 8 -> 8, relu (all-smem weights, ic-unroll-4, occ-5)
    float* src = bufA;
    float* dst = bufB;
    for (int l = 0; l < 18; ++l) {
        convv8_kernel<8, 4, 5><<<grid, 256>>>(src, dst, l * 576);
        float* t = src; src = dst; dst = t;
    }

    // conv20: 8 -> 1, no relu
    convv20_kernel<<<grid, 256>>>(src, out);
}

// round 17
// speedup vs baseline: 1.3574x; 1.3559x over previous
#include <cuda_runtime.h>
#include <cuda_bf16.h>

// SmallVDSR via warp-level mma.sync bf16-split tensor conv (sm_103 baseline ISA).
//  Inter-layer activations: 32B/px records [hi8 bf16, lo8 bf16], pixel-major.
//  conv1 (fp32 direct) -> records; 18x mma mid layers; conv20 records -> fp32.

#define H 512
#define W 512
#define NB 8
#define PLANE (H * W)

typedef unsigned int u32;

__device__ u32 g_r0[NB * PLANE * 8];   // ping records (8 u32 per px)
__device__ u32 g_r1[NB * PLANE * 8];   // pong records

__device__ __forceinline__ u32 smem_u32(const void* p) {
    u32 a;
    asm("{ .reg .u64 t; cvta.to.shared.u64 t, %1; cvt.u32.u64 %0, t; }" : "=r"(a) : "l"(p));
    return a;
}

// ---------------------------------------------------------------------------
// conv1: fp32 plane -> records (1->8, relu)
// ---------------------------------------------------------------------------
__global__ void __launch_bounds__(256) conv1_k(const float* __restrict__ x,
                                               const float* __restrict__ w1,
                                               u32* __restrict__ rout)
{
    __shared__ float s_w[72];
    int tid = threadIdx.x;
    if (tid < 72) s_w[tid] = w1[tid];                  // [oc][k]
    __syncthreads();
    int p = blockIdx.x * 256 + tid;
    int n = p >> 18, yx = p & (PLANE - 1), y = yx >> 9, xx = yx & 511;
    const float* xp = x + (size_t)n * PLANE;
    float acc[8];
    #pragma unroll
    for (int j = 0; j < 8; ++j) acc[j] = 0.0f;
    #pragma unroll
    for (int ky = 0; ky < 3; ++ky) {
        int gy = y + ky - 1;
        if (gy < 0 || gy >= H) continue;
        #pragma unroll
        for (int kx = 0; kx < 3; ++kx) {
            int gx = xx + kx - 1;
            if (gx < 0 || gx >= W) continue;
            float v = __ldg(xp + gy * W + gx);
            #pragma unroll
            for (int oc = 0; oc < 8; ++oc)
                acc[oc] = fmaf(v, s_w[oc * 9 + ky * 3 + kx], acc[oc]);
        }
    }
    u32 rec[8];
    #pragma unroll
    for (int j = 0; j < 4; ++j) {
        float a = fmaxf(acc[2 * j], 0.f), b = fmaxf(acc[2 * j + 1], 0.f);
        __nv_bfloat162 h = __floats2bfloat162_rn(a, b);
        __nv_bfloat162 l = __floats2bfloat162_rn(a - __bfloat162float(h.x),
                                                 b - __bfloat162float(h.y));
        rec[j] = *(u32*)&h;
        rec[4 + j] = *(u32*)&l;
    }
    uint4* op = (uint4*)(rout + (size_t)p * 8);
    op[0] = *(uint4*)&rec[0];
    op[1] = *(uint4*)&rec[4];
}

// ---------------------------------------------------------------------------
// Mid layers: mma.sync m16n8k16 bf16, split precision.
// Tile 64x8 px, block 256 (8 warps x 1 row x 4 chunks of 16 px).
// SMEM: 10 strips x 66 records, 48B stride (conflict-free ldmatrix).
// ---------------------------------------------------------------------------
#define TILE_W 64
#define SCOLS  66
#define SSTRIDE 48
#define SSTRIP (SCOLS * SSTRIDE)   // 3168

__global__ void __launch_bounds__(256, 4)
convmma_k(const u32* __restrict__ rin, u32* __restrict__ rout,
          const float* __restrict__ wmid, int layer)
{
    __shared__ __align__(16) char sA[10 * SSTRIP];     // 31680 B

    const int tid = threadIdx.x, wid = tid >> 5, lane = tid & 31;
    const int n = blockIdx.z, gx0 = blockIdx.x * TILE_W, gy0 = blockIdx.y * 8;
    const int q = lane & 3, g = lane >> 2;

    // --- B fragments in registers: thread owns oc n=g, ic pair (2q, 2q+1) ---
    u32 bhi[9], blo[9];
    {
        const float* wp = wmid + (size_t)(layer * 8 + g) * 8 * 9;   // [oc=g][ic][tap]
        #pragma unroll
        for (int t = 0; t < 9; ++t) {
            float w0 = wp[(2 * q) * 9 + t];
            float w1 = wp[(2 * q + 1) * 9 + t];
            __nv_bfloat162 h = __floats2bfloat162_rn(w0, w1);
            __nv_bfloat162 l = __floats2bfloat162_rn(w0 - __bfloat162float(h.x),
                                                     w1 - __bfloat162float(h.y));
            bhi[t] = *(u32*)&h;
            blo[t] = *(u32*)&l;
        }
    }

    // --- stage 10 x 66 records (zero halo) ---
    for (int i = tid; i < 660; i += 256) {
        int rr = i / SCOLS, cc = i - rr * SCOLS;
        int gy = gy0 + rr - 1, gx = gx0 + cc - 1;
        uint4 hi = make_uint4(0, 0, 0, 0), lo = make_uint4(0, 0, 0, 0);
        if (gy >= 0 && gy < H && gx >= 0 && gx < W) {
            const uint4* rp = (const uint4*)(rin + ((size_t)n * PLANE + gy * W + gx) * 8);
            hi = rp[0];
            lo = rp[1];
        }
        char* d = sA + rr * SSTRIP + cc * SSTRIDE;
        *(uint4*)d = hi;
        *(uint4*)(d + 16) = lo;
    }
    __syncthreads();

    // per-thread ldmatrix row base: rows = pixels (t&15), halves = hi/lo (t>>4)
    const u32 abase = smem_u32(sA) + (lane & 15) * SSTRIDE + (lane >> 4) * 16 + wid * SSTRIP;
    const int gy = gy0 + wid;
    u32* outb = rout + ((size_t)n * PLANE + (size_t)gy * W + gx0) * 8;

    #pragma unroll 1
    for (int c = 0; c < TILE_W / 16; ++c) {
        float cA0 = 0.f, cA1 = 0.f, cA2 = 0.f, cA3 = 0.f;   // Whi-step acc
        float cB0 = 0.f, cB1 = 0.f, cB2 = 0.f, cB3 = 0.f;   // Wlo-step acc
        const u32 cb = abase + c * 16 * SSTRIDE;
        #pragma unroll
        for (int ky = 0; ky < 3; ++ky) {
            #pragma unroll
            for (int kx = 0; kx < 3; ++kx) {
                const int t = ky * 3 + kx;
                u32 addr = cb + ky * SSTRIP + kx * SSTRIDE;
                u32 a0, a1, a2, a3;
                asm volatile(
                    "ldmatrix.sync.aligned.m8n8.x4.shared.b16 {%0,%1,%2,%3}, [%4];"
                    : "=r"(a0), "=r"(a1), "=r"(a2), "=r"(a3) : "r"(addr));
                asm volatile(
                    "mma.sync.aligned.m16n8k16.row.col.f32.bf16.bf16.f32 "
                    "{%0,%1,%2,%3}, {%4,%5,%6,%7}, {%8,%9}, {%0,%1,%2,%3};"
                    : "+f"(cA0), "+f"(cA1), "+f"(cA2), "+f"(cA3)
                    : "r"(a0), "r"(a1), "r"(a2), "r"(a3), "r"(bhi[t]), "r"(bhi[t]));
                asm volatile(
                    "mma.sync.aligned.m16n8k16.row.col.f32.bf16.bf16.f32 "
                    "{%0,%1,%2,%3}, {%4,%5,%6,%7}, {%8,%9}, {%0,%1,%2,%3};"
                    : "+f"(cB0), "+f"(cB1), "+f"(cB2), "+f"(cB3)
                    : "r"(a0), "r"(a1), "r"(a2), "r"(a3), "r"(blo[t]), "r"(blo[t]));
            }
        }
        // epilogue: relu, fp32 -> hi/lo bf16 records
        float f0 = fmaxf(cA0 + cB0, 0.f), f1 = fmaxf(cA1 + cB1, 0.f);
        float f2 = fmaxf(cA2 + cB2, 0.f), f3 = fmaxf(cA3 + cB3, 0.f);
        __nv_bfloat162 h0 = __floats2bfloat162_rn(f0, f1);
        __nv_bfloat162 l0 = __floats2bfloat162_rn(f0 - __bfloat162float(h0.x),
                                                  f1 - __bfloat162float(h0.y));
        __nv_bfloat162 h1 = __floats2bfloat162_rn(f2, f3);
        __nv_bfloat162 l1 = __floats2bfloat162_rn(f2 - __bfloat162float(h1.x),
                                                  f3 - __bfloat162float(h1.y));
        u32* r0p = outb + (size_t)(c * 16 + g) * 8;        // pixel g, ocs 2q,2q+1
        u32* r1p = outb + (size_t)(c * 16 + g + 8) * 8;    // pixel g+8
        r0p[q]     = *(u32*)&h0;
        r0p[4 + q] = *(u32*)&l0;
        r1p[q]     = *(u32*)&h1;
        r1p[4 + q] = *(u32*)&l1;
    }
}

// ---------------------------------------------------------------------------
// conv20: records -> fp32 (8->1, no relu)
// ---------------------------------------------------------------------------
__global__ void __launch_bounds__(256) conv20_k(const u32* __restrict__ rin,
                                                const float* __restrict__ w20,
                                                float* __restrict__ out)
{
    __shared__ float s_w[72];
    int tid = threadIdx.x;
    if (tid < 72) s_w[tid] = w20[tid];                 // [ic][k]
    __syncthreads();
    int p = blockIdx.x * 256 + tid;
    int n = p >> 18, yx = p & (PLANE - 1), y = yx >> 9, xx = yx & 511;
    float acc = 0.0f;
    #pragma unroll
    for (int ky = 0; ky < 3; ++ky) {
        int gy = y + ky - 1;
        if (gy < 0 || gy >= H) continue;
        #pragma unroll
        for (int kx = 0; kx < 3; ++kx) {
            int gx = xx + kx - 1;
            if (gx < 0 || gx >= W) continue;
            const uint4* rp = (const uint4*)(rin + ((size_t)n * PLANE + gy * W + gx) * 8);
            uint4 hi = rp[0], lo = rp[1];
            u32 ha[4] = {hi.x, hi.y, hi.z, hi.w}, la[4] = {lo.x, lo.y, lo.z, lo.w};
            int k = ky * 3 + kx;
            #pragma unroll
            for (int j = 0; j < 4; ++j) {
                float2 fh = __bfloat1622float2(*(__nv_bfloat162*)&ha[j]);
                float2 fl = __bfloat1622float2(*(__nv_bfloat162*)&la[j]);
                acc = fmaf(fh.x + fl.x, s_w[(2 * j) * 9 + k], acc);
                acc = fmaf(fh.y + fl.y, s_w[(2 * j + 1) * 9 + k], acc);
            }
        }
    }
    out[p] = acc;
}

extern "C" void kernel_launch(void* const* d_in, const int* in_sizes, int n_in,
                              void* d_out, int out_size)
{
    const float* x    = (const float*)d_in[0];  // [8,1,512,512]
    const float* w1   = (const float*)d_in[1];  // [8,1,3,3]
    const float* wmid = (const float*)d_in[2];  // [18,8,8,3,3]
    const float* w20  = (const float*)d_in[3];  // [1,8,3,3]
    float* out = (float*)d_out;

    u32 *r0 = nullptr, *r1 = nullptr;
    cudaGetSymbolAddress((void**)&r0, g_r0);
    cudaGetSymbolAddress((void**)&r1, g_r1);

    // conv1: 1 -> 8 relu, fp32 -> records
    conv1_k<<<NB * PLANE / 256, 256>>>(x, w1, r0);

    // conv2..19: mma.sync bf16-split
    dim3 grid(W / TILE_W, H / 8, NB);
    u32 *src = r0, *dst = r1;
    for (int l = 0; l < 18; ++l) {
        convmma_k<<<grid, 256>>>(src, dst, wmid, l);
        u32* t = src; src = dst; dst = t;
    }

    // conv20: 8 -> 1, no relu, records -> fp32
    conv20_k<<<NB * PLANE / 256, 256>>>(src, w20, out);
}